// round 14
// baseline (speedup 1.0000x reference)
#include <cuda_runtime.h>
#include <cuda_fp16.h>
#include <cstdint>

// ---------------------------------------------------------------------------
// Edge-MLP link predictor, factorized + tensor-core phase 1:
//   P[n][0:128]   = h[n] @ W1[0:128,:]   + b1   (Pa, fp16, PERMUTED layout)
//   P[n][128:256] = h[n] @ W1[128:256,:]        (Pb, fp16, PERMUTED layout)
//   out[e] = sigmoid( relu(Pa[src_e] + Pb[dst_e]) . W2 + b2 )
// Phase 2: 8 lanes/edge, 12 edges/warp (3 batches of 4; all 24 gather
// LDG.128 issued before compute -> ~288 loads in flight per SM).
// Lane l8 loads 16B at l8*16 and 128+l8*16 -> one 128B line per LDG per
// edge (4 wavefronts/edge = floor). W2 permuted in SMEM.
// ---------------------------------------------------------------------------

static constexpr int HID = 128;
static constexpr int MAXN = 50000;

__device__ __half g_P[(size_t)MAXN * 256];

// ---------------- helpers ----------------

__device__ __forceinline__ uint32_t smem_u32(const void* p) {
    uint32_t a;
    asm("{ .reg .u64 t; cvta.to.shared.u64 t, %1; cvt.u32.u64 %0, t; }"
        : "=r"(a) : "l"(p));
    return a;
}

__device__ __forceinline__ uint32_t h2_bits(__half2 h) {
    return *reinterpret_cast<uint32_t*>(&h);
}

__device__ __forceinline__ void ldm_x4(uint32_t& a0, uint32_t& a1, uint32_t& a2,
                                       uint32_t& a3, uint32_t addr) {
    asm volatile("ldmatrix.sync.aligned.m8n8.x4.shared.b16 {%0,%1,%2,%3}, [%4];"
                 : "=r"(a0), "=r"(a1), "=r"(a2), "=r"(a3) : "r"(addr));
}

__device__ __forceinline__ void ldm_x4_t(uint32_t& b0, uint32_t& b1, uint32_t& b2,
                                         uint32_t& b3, uint32_t addr) {
    asm volatile("ldmatrix.sync.aligned.m8n8.x4.trans.shared.b16 {%0,%1,%2,%3}, [%4];"
                 : "=r"(b0), "=r"(b1), "=r"(b2), "=r"(b3) : "r"(addr));
}

__device__ __forceinline__ void mma16816(float& d0, float& d1, float& d2, float& d3,
                                         uint32_t a0, uint32_t a1, uint32_t a2,
                                         uint32_t a3, uint32_t b0, uint32_t b1) {
    asm volatile(
        "mma.sync.aligned.m16n8k16.row.col.f32.f16.f16.f32 "
        "{%0,%1,%2,%3}, {%4,%5,%6,%7}, {%8,%9}, {%0,%1,%2,%3};"
        : "+f"(d0), "+f"(d1), "+f"(d2), "+f"(d3)
        : "r"(a0), "r"(a1), "r"(a2), "r"(a3), "r"(b0), "r"(b1));
}

// ---------------- Phase 1: persistent node projection GEMM ----------------
// (at legacy-HMMA pipe peak ~330 TF/s; unchanged)

static constexpr int SROW = 136;
static constexpr uint32_t SROWB = SROW * 2;      // 272 bytes
static constexpr uint32_t AS_BYTES = 64u * SROWB;
static constexpr uint32_t BS_BYTES = 256u * SROWB;
static constexpr uint32_t P1_SMEM  = AS_BYTES + BS_BYTES;   // 87040 B

__global__ void __launch_bounds__(256, 1)
node_proj_kernel(const float* __restrict__ hfeat,
                 const float* __restrict__ W1,   // [256,128] row-major
                 const float* __restrict__ b1,   // [128]
                 int M, int n_tiles) {
    extern __shared__ __align__(16) char smem[];
    char* As = smem;                          // [64][SROW] halfs, row = m
    char* Bs = smem + AS_BYTES;               // [256][SROW] halfs
    const uint32_t as_b = smem_u32(As);
    const uint32_t bs_b = smem_u32(Bs);

    const int tid = threadIdx.x;
    const int wid  = tid >> 5;
    const int lane = tid & 31;
    const int wm = (wid >> 2) * 32;
    const int wn = (wid & 3) * 32;
    const int l15 = lane & 15;
    const int khalf = (lane >> 4) * 8;
    const int r0 = lane >> 2;
    const int c0 = (lane & 3) * 2;
    const int brow = ((lane >> 3) & 1) * 8 + (lane & 7);
    const int bcol = (lane >> 4) * 8;

    // ---- load W1 (both halves) once ----
    #pragma unroll
    for (int it = 0; it < 32; it++) {
        int i  = tid + it * 256;
        int r  = i >> 5;
        int c4 = i & 31;
        float4 vb = reinterpret_cast<const float4*>(W1)[(size_t)r * 32 + c4];
        *reinterpret_cast<uint2*>(Bs + r * SROWB + c4 * 8) =
            make_uint2(h2_bits(__floats2half2_rn(vb.x, vb.y)),
                       h2_bits(__floats2half2_rn(vb.z, vb.w)));
    }

    const int ar  = tid >> 5;
    const int ac4 = tid & 31;

    int tile = blockIdx.x;
    float4 va[8];
    if (tile < n_tiles) {
        const int m0 = tile * 64;
        #pragma unroll
        for (int it = 0; it < 8; it++) {
            int r = ar + it * 8;
            int gm = m0 + r; if (gm >= M) gm = M - 1;
            va[it] = reinterpret_cast<const float4*>(hfeat)[(size_t)gm * 32 + ac4];
        }
    }

    while (tile < n_tiles) {
        const int m0 = tile * 64;
        const int next = tile + gridDim.x;

        __syncthreads();
        #pragma unroll
        for (int it = 0; it < 8; it++) {
            int r = ar + it * 8;
            *reinterpret_cast<uint2*>(As + r * SROWB + ac4 * 8) =
                make_uint2(h2_bits(__floats2half2_rn(va[it].x, va[it].y)),
                           h2_bits(__floats2half2_rn(va[it].z, va[it].w)));
        }
        __syncthreads();

        if (next < n_tiles) {
            const int m1 = next * 64;
            #pragma unroll
            for (int it = 0; it < 8; it++) {
                int r = ar + it * 8;
                int gm = m1 + r; if (gm >= M) gm = M - 1;
                va[it] = reinterpret_cast<const float4*>(hfeat)[(size_t)gm * 32 + ac4];
            }
        }

        #pragma unroll
        for (int half = 0; half < 2; half++) {
            float d[2][4][4];
            #pragma unroll
            for (int fm = 0; fm < 2; fm++)
                #pragma unroll
                for (int fn = 0; fn < 4; fn++)
                    #pragma unroll
                    for (int r = 0; r < 4; r++) d[fm][fn][r] = 0.0f;

            const uint32_t bs_h = bs_b + (uint32_t)(half * 128) * SROWB;

            #pragma unroll
            for (int kk = 0; kk < 8; kk++) {
                const int k16 = kk * 16;
                uint32_t a[2][4];
                #pragma unroll
                for (int fm = 0; fm < 2; fm++) {
                    uint32_t addr = as_b + (uint32_t)(wm + fm * 16 + l15) * SROWB +
                                    (uint32_t)(k16 + khalf) * 2;
                    ldm_x4(a[fm][0], a[fm][1], a[fm][2], a[fm][3], addr);
                }
                uint32_t b[4][2];
                #pragma unroll
                for (int fnp = 0; fnp < 2; fnp++) {
                    uint32_t addr = bs_h + (uint32_t)(k16 + brow) * SROWB +
                                    (uint32_t)(wn + fnp * 16 + bcol) * 2;
                    ldm_x4_t(b[2 * fnp][0], b[2 * fnp][1],
                             b[2 * fnp + 1][0], b[2 * fnp + 1][1], addr);
                }
                #pragma unroll
                for (int fm = 0; fm < 2; fm++)
                    #pragma unroll
                    for (int fn = 0; fn < 4; fn++)
                        mma16816(d[fm][fn][0], d[fm][fn][1], d[fm][fn][2], d[fm][fn][3],
                                 a[fm][0], a[fm][1], a[fm][2], a[fm][3],
                                 b[fn][0], b[fn][1]);
            }

            // epilogue: +b1, pack 8 halfs, one coalesced STG.128 per (fm,sub)
            float2 bias[4];
            #pragma unroll
            for (int fn = 0; fn < 4; fn++) {
                bias[fn] = (half == 0)
                    ? *reinterpret_cast<const float2*>(b1 + wn + fn * 8 + c0)
                    : make_float2(0.0f, 0.0f);
            }
            #pragma unroll
            for (int fm = 0; fm < 2; fm++) {
                #pragma unroll
                for (int sub = 0; sub < 2; sub++) {
                    int gm = m0 + wm + fm * 16 + r0 + sub * 8;
                    if (gm < M) {
                        uint32_t z[4];
                        #pragma unroll
                        for (int fn = 0; fn < 4; fn++) {
                            float x = d[fm][fn][sub * 2]     + bias[fn].x;
                            float y = d[fm][fn][sub * 2 + 1] + bias[fn].y;
                            z[fn] = h2_bits(__floats2half2_rn(x, y));
                        }
                        char* dst = reinterpret_cast<char*>(g_P) +
                                    (size_t)gm * 512 + half * 256 + wn * 2 +
                                    (lane & 3) * 16;
                        *reinterpret_cast<uint4*>(dst) = make_uint4(z[0], z[1], z[2], z[3]);
                    }
                }
            }
        }
        tile = next;
    }
}

// ---------------- Phase 2: 12 edges/warp, 8 lanes/edge, line-contiguous ----------------

__global__ void __launch_bounds__(256)
edge_kernel(const int* __restrict__ eidx,    // [2, E] int32
            const float* __restrict__ W2,    // [128]
            const float* __restrict__ b2,    // [1]
            float* __restrict__ out, int E) {
    __shared__ __align__(16) __half w2s[128];

    const int tid  = threadIdx.x;
    if (tid < 128) {
        int q = tid & 31;
        int j = (tid & ~31) + ((q >> 1) & 3) * 8 + (q >> 3) * 2 + (q & 1);
        w2s[tid] = __float2half_rn(__ldg(W2 + j));
    }
    __syncthreads();

    const int warp = (blockIdx.x * blockDim.x + tid) >> 5;
    const int lane = tid & 31;
    const int g  = lane >> 3;                // edge group 0..3
    const int l8 = lane & 7;                 // position within edge
    const int e0 = warp * 12;                // 12 edges per warp (3 batches of 4)
    if (e0 >= E) return;

    // lane's W2 chunks: permuted halfs [l8*8, +8) and [64+l8*8, +8)
    const char* w2c = reinterpret_cast<const char*>(w2s);
    uint4 wq0 = *reinterpret_cast<const uint4*>(w2c + l8 * 16);
    uint4 wq1 = *reinterpret_cast<const uint4*>(w2c + 128 + l8 * 16);
    const uint32_t* w2p0 = &wq0.x;
    const uint32_t* w2p1 = &wq1.x;

    const char* Pbase = reinterpret_cast<const char*>(g_P);
    const uint32_t loff = (uint32_t)l8 << 4;   // 16B chunk within 128B line

    // indices for all 3 batches
    int ev[3];
    bool ok[3];
    const char* pa[3];
    const char* pb[3];
    #pragma unroll
    for (int i = 0; i < 3; i++) {
        ev[i] = e0 + i * 4 + g;
        ok[i] = ev[i] < E;
        int sv = ok[i] ? __ldg(eidx + ev[i]) : 0;
        int dv = ok[i] ? __ldg(eidx + E + ev[i]) : 0;
        pa[i] = Pbase + (((uint32_t)sv << 9) + loff);
        pb[i] = Pbase + (((uint32_t)dv << 9) + 256u + loff);
    }

    // issue all 24 gathers before any compute (one 128B line per LDG per edge)
    uint4 a0[3], a1[3], b0[3], b1[3];
    #pragma unroll
    for (int i = 0; i < 3; i++) {
        a0[i] = *reinterpret_cast<const uint4*>(pa[i]);
        a1[i] = *reinterpret_cast<const uint4*>(pa[i] + 128);
        b0[i] = *reinterpret_cast<const uint4*>(pb[i]);
        b1[i] = *reinterpret_cast<const uint4*>(pb[i] + 128);
    }

    const __half2 z2 = __float2half2_rn(0.0f);

    float acc[3];
    #pragma unroll
    for (int i = 0; i < 3; i++) {
        const uint32_t* qa0 = &a0[i].x;
        const uint32_t* qa1 = &a1[i].x;
        const uint32_t* qb0 = &b0[i].x;
        const uint32_t* qb1 = &b1[i].x;
        __half2 t = __hmul2(__hmax2(__hadd2(*reinterpret_cast<const __half2*>(&qa0[0]),
                                            *reinterpret_cast<const __half2*>(&qb0[0])), z2),
                            *reinterpret_cast<const __half2*>(&w2p0[0]));
        #pragma unroll
        for (int q = 1; q < 4; q++)
            t = __hfma2(__hmax2(__hadd2(*reinterpret_cast<const __half2*>(&qa0[q]),
                                        *reinterpret_cast<const __half2*>(&qb0[q])), z2),
                        *reinterpret_cast<const __half2*>(&w2p0[q]), t);
        #pragma unroll
        for (int q = 0; q < 4; q++)
            t = __hfma2(__hmax2(__hadd2(*reinterpret_cast<const __half2*>(&qa1[q]),
                                        *reinterpret_cast<const __half2*>(&qb1[q])), z2),
                        *reinterpret_cast<const __half2*>(&w2p1[q]), t);
        float2 f = __half22float2(t);
        acc[i] = f.x + f.y;
    }

    #pragma unroll
    for (int off = 4; off > 0; off >>= 1) {
        #pragma unroll
        for (int i = 0; i < 3; i++)
            acc[i] += __shfl_xor_sync(0xFFFFFFFFu, acc[i], off);
    }

    if (l8 == 0) {
        const float b2v = __ldg(b2);
        #pragma unroll
        for (int i = 0; i < 3; i++)
            if (ok[i]) out[ev[i]] = 1.0f / (1.0f + __expf(-(acc[i] + b2v)));
    }
}

// ---------------- launch ----------------

extern "C" void kernel_launch(void* const* d_in, const int* in_sizes, int n_in,
                              void* d_out, int out_size) {
    const float* hfeat = (const float*)d_in[0];
    const int*   eidx  = (const int*)d_in[1];
    const float* W1    = (const float*)d_in[2];
    const float* b1    = (const float*)d_in[3];
    const float* W2    = (const float*)d_in[4];
    const float* b2    = (const float*)d_in[5];
    float* out = (float*)d_out;

    const int M = in_sizes[0] / HID;
    const int E = in_sizes[1] / 2;
    const int n_tiles = (M + 63) / 64;

    cudaFuncSetAttribute(node_proj_kernel,
                         cudaFuncAttributeMaxDynamicSharedMemorySize, (int)P1_SMEM);

    int grid1 = 148;                         // 1 CTA/SM: W1 loaded once per SM
    if (grid1 > n_tiles) grid1 = n_tiles;
    node_proj_kernel<<<grid1, 256, P1_SMEM>>>(hfeat, W1, b1, M, n_tiles);

    const int warps = (E + 11) / 12;         // 12 edges per warp
    const int blocks = (warps + 7) / 8;
    edge_kernel<<<blocks, 256>>>(eidx, W2, b2, out, E);
}

// round 15
// speedup vs baseline: 1.0300x; 1.0300x over previous
#include <cuda_runtime.h>
#include <cuda_fp16.h>
#include <cstdint>

// ---------------------------------------------------------------------------
// Edge-MLP link predictor, factorized + tensor-core phase 1:
//   P[n][0:128]   = h[n] @ W1[0:128,:]   + b1   (Pa, fp16, PERMUTED layout)
//   P[n][128:256] = h[n] @ W1[128:256,:]        (Pb, fp16, PERMUTED layout)
//   out[e] = sigmoid( relu(Pa[src_e] + Pb[dst_e]) . W2 + b2 )
// Phase 1: persistent CTAs, W1 SMEM-resident, DOUBLE-BUFFERED A tiles ->
//          one __syncthreads per tile, LDG(t+1) overlaps MMA(t).
// Phase 2: 8 lanes/edge, 12 edges/warp, line-contiguous gathers
//          (one 128B line per LDG per edge = 4 wavefronts/edge floor).
// ---------------------------------------------------------------------------

static constexpr int HID = 128;
static constexpr int MAXN = 50000;

__device__ __half g_P[(size_t)MAXN * 256];

// ---------------- helpers ----------------

__device__ __forceinline__ uint32_t smem_u32(const void* p) {
    uint32_t a;
    asm("{ .reg .u64 t; cvta.to.shared.u64 t, %1; cvt.u32.u64 %0, t; }"
        : "=r"(a) : "l"(p));
    return a;
}

__device__ __forceinline__ uint32_t h2_bits(__half2 h) {
    return *reinterpret_cast<uint32_t*>(&h);
}

__device__ __forceinline__ void ldm_x4(uint32_t& a0, uint32_t& a1, uint32_t& a2,
                                       uint32_t& a3, uint32_t addr) {
    asm volatile("ldmatrix.sync.aligned.m8n8.x4.shared.b16 {%0,%1,%2,%3}, [%4];"
                 : "=r"(a0), "=r"(a1), "=r"(a2), "=r"(a3) : "r"(addr));
}

__device__ __forceinline__ void ldm_x4_t(uint32_t& b0, uint32_t& b1, uint32_t& b2,
                                         uint32_t& b3, uint32_t addr) {
    asm volatile("ldmatrix.sync.aligned.m8n8.x4.trans.shared.b16 {%0,%1,%2,%3}, [%4];"
                 : "=r"(b0), "=r"(b1), "=r"(b2), "=r"(b3) : "r"(addr));
}

__device__ __forceinline__ void mma16816(float& d0, float& d1, float& d2, float& d3,
                                         uint32_t a0, uint32_t a1, uint32_t a2,
                                         uint32_t a3, uint32_t b0, uint32_t b1) {
    asm volatile(
        "mma.sync.aligned.m16n8k16.row.col.f32.f16.f16.f32 "
        "{%0,%1,%2,%3}, {%4,%5,%6,%7}, {%8,%9}, {%0,%1,%2,%3};"
        : "+f"(d0), "+f"(d1), "+f"(d2), "+f"(d3)
        : "r"(a0), "r"(a1), "r"(a2), "r"(a3), "r"(b0), "r"(b1));
}

// ---------------- Phase 1: persistent node projection GEMM ----------------

static constexpr int SROW = 136;
static constexpr uint32_t SROWB = SROW * 2;      // 272 bytes
static constexpr uint32_t AS_BYTES = 64u * SROWB;        // 17408
static constexpr uint32_t BS_BYTES = 256u * SROWB;       // 69632
static constexpr uint32_t P1_SMEM  = 2u * AS_BYTES + BS_BYTES;  // 104448

__global__ void __launch_bounds__(256, 1)
node_proj_kernel(const float* __restrict__ hfeat,
                 const float* __restrict__ W1,   // [256,128] row-major
                 const float* __restrict__ b1,   // [128]
                 int M, int n_tiles) {
    extern __shared__ __align__(16) char smem[];
    char* Bs = smem + 2 * AS_BYTES;           // [256][SROW] halfs
    const uint32_t as_b = smem_u32(smem);
    const uint32_t bs_b = smem_u32(Bs);

    const int tid = threadIdx.x;
    const int wid  = tid >> 5;
    const int lane = tid & 31;
    const int wm = (wid >> 2) * 32;
    const int wn = (wid & 3) * 32;
    const int l15 = lane & 15;
    const int khalf = (lane >> 4) * 8;
    const int r0 = lane >> 2;
    const int c0 = (lane & 3) * 2;
    const int brow = ((lane >> 3) & 1) * 8 + (lane & 7);
    const int bcol = (lane >> 4) * 8;

    // ---- load W1 (both halves) once ----
    #pragma unroll
    for (int it = 0; it < 32; it++) {
        int i  = tid + it * 256;
        int r  = i >> 5;
        int c4 = i & 31;
        float4 vb = reinterpret_cast<const float4*>(W1)[(size_t)r * 32 + c4];
        *reinterpret_cast<uint2*>(Bs + r * SROWB + c4 * 8) =
            make_uint2(h2_bits(__floats2half2_rn(vb.x, vb.y)),
                       h2_bits(__floats2half2_rn(vb.z, vb.w)));
    }

    const int ar  = tid >> 5;
    const int ac4 = tid & 31;

    int tile = blockIdx.x;
    int buf  = 0;
    float4 va[8];
    if (tile < n_tiles) {
        const int m0 = tile * 64;
        #pragma unroll
        for (int it = 0; it < 8; it++) {
            int r = ar + it * 8;
            int gm = m0 + r; if (gm >= M) gm = M - 1;
            va[it] = reinterpret_cast<const float4*>(hfeat)[(size_t)gm * 32 + ac4];
        }
    }

    while (tile < n_tiles) {
        const int m0 = tile * 64;
        const int next = tile + gridDim.x;
        char* Acur = smem + buf * AS_BYTES;
        const uint32_t as_cur = as_b + buf * AS_BYTES;

        // STS into current buffer (other buffer's readers finished: proven by
        // the PREVIOUS iteration's sync). One barrier per tile.
        #pragma unroll
        for (int it = 0; it < 8; it++) {
            int r = ar + it * 8;
            *reinterpret_cast<uint2*>(Acur + r * SROWB + ac4 * 8) =
                make_uint2(h2_bits(__floats2half2_rn(va[it].x, va[it].y)),
                           h2_bits(__floats2half2_rn(va[it].z, va[it].w)));
        }
        __syncthreads();   // covers W1 STS on first iteration too

        // prefetch next tile's A while MMA runs
        if (next < n_tiles) {
            const int m1 = next * 64;
            #pragma unroll
            for (int it = 0; it < 8; it++) {
                int r = ar + it * 8;
                int gm = m1 + r; if (gm >= M) gm = M - 1;
                va[it] = reinterpret_cast<const float4*>(hfeat)[(size_t)gm * 32 + ac4];
            }
        }

        #pragma unroll
        for (int half = 0; half < 2; half++) {
            float d[2][4][4];
            #pragma unroll
            for (int fm = 0; fm < 2; fm++)
                #pragma unroll
                for (int fn = 0; fn < 4; fn++)
                    #pragma unroll
                    for (int r = 0; r < 4; r++) d[fm][fn][r] = 0.0f;

            const uint32_t bs_h = bs_b + (uint32_t)(half * 128) * SROWB;

            #pragma unroll
            for (int kk = 0; kk < 8; kk++) {
                const int k16 = kk * 16;
                uint32_t a[2][4];
                #pragma unroll
                for (int fm = 0; fm < 2; fm++) {
                    uint32_t addr = as_cur + (uint32_t)(wm + fm * 16 + l15) * SROWB +
                                    (uint32_t)(k16 + khalf) * 2;
                    ldm_x4(a[fm][0], a[fm][1], a[fm][2], a[fm][3], addr);
                }
                uint32_t b[4][2];
                #pragma unroll
                for (int fnp = 0; fnp < 2; fnp++) {
                    uint32_t addr = bs_h + (uint32_t)(k16 + brow) * SROWB +
                                    (uint32_t)(wn + fnp * 16 + bcol) * 2;
                    ldm_x4_t(b[2 * fnp][0], b[2 * fnp][1],
                             b[2 * fnp + 1][0], b[2 * fnp + 1][1], addr);
                }
                #pragma unroll
                for (int fm = 0; fm < 2; fm++)
                    #pragma unroll
                    for (int fn = 0; fn < 4; fn++)
                        mma16816(d[fm][fn][0], d[fm][fn][1], d[fm][fn][2], d[fm][fn][3],
                                 a[fm][0], a[fm][1], a[fm][2], a[fm][3],
                                 b[fn][0], b[fn][1]);
            }

            // epilogue: +b1, pack 8 halfs, one coalesced STG.128 per (fm,sub)
            float2 bias[4];
            #pragma unroll
            for (int fn = 0; fn < 4; fn++) {
                bias[fn] = (half == 0)
                    ? *reinterpret_cast<const float2*>(b1 + wn + fn * 8 + c0)
                    : make_float2(0.0f, 0.0f);
            }
            #pragma unroll
            for (int fm = 0; fm < 2; fm++) {
                #pragma unroll
                for (int sub = 0; sub < 2; sub++) {
                    int gm = m0 + wm + fm * 16 + r0 + sub * 8;
                    if (gm < M) {
                        uint32_t z[4];
                        #pragma unroll
                        for (int fn = 0; fn < 4; fn++) {
                            float x = d[fm][fn][sub * 2]     + bias[fn].x;
                            float y = d[fm][fn][sub * 2 + 1] + bias[fn].y;
                            z[fn] = h2_bits(__floats2half2_rn(x, y));
                        }
                        char* dst = reinterpret_cast<char*>(g_P) +
                                    (size_t)gm * 512 + half * 256 + wn * 2 +
                                    (lane & 3) * 16;
                        *reinterpret_cast<uint4*>(dst) = make_uint4(z[0], z[1], z[2], z[3]);
                    }
                }
            }
        }
        buf ^= 1;
        tile = next;
    }
}

// ---------------- Phase 2: 12 edges/warp, 8 lanes/edge, line-contiguous ----------------

__global__ void __launch_bounds__(256)
edge_kernel(const int* __restrict__ eidx,    // [2, E] int32
            const float* __restrict__ W2,    // [128]
            const float* __restrict__ b2,    // [1]
            float* __restrict__ out, int E) {
    __shared__ __align__(16) __half w2s[128];

    const int tid  = threadIdx.x;
    if (tid < 128) {
        int q = tid & 31;
        int j = (tid & ~31) + ((q >> 1) & 3) * 8 + (q >> 3) * 2 + (q & 1);
        w2s[tid] = __float2half_rn(__ldg(W2 + j));
    }
    __syncthreads();

    const int warp = (blockIdx.x * blockDim.x + tid) >> 5;
    const int lane = tid & 31;
    const int g  = lane >> 3;                // edge group 0..3
    const int l8 = lane & 7;                 // position within edge
    const int e0 = warp * 12;                // 12 edges per warp (3 batches of 4)
    if (e0 >= E) return;

    const char* w2c = reinterpret_cast<const char*>(w2s);
    uint4 wq0 = *reinterpret_cast<const uint4*>(w2c + l8 * 16);
    uint4 wq1 = *reinterpret_cast<const uint4*>(w2c + 128 + l8 * 16);
    const uint32_t* w2p0 = &wq0.x;
    const uint32_t* w2p1 = &wq1.x;

    const char* Pbase = reinterpret_cast<const char*>(g_P);
    const uint32_t loff = (uint32_t)l8 << 4;   // 16B chunk within 128B line

    int ev[3];
    bool ok[3];
    const char* pa[3];
    const char* pb[3];
    #pragma unroll
    for (int i = 0; i < 3; i++) {
        ev[i] = e0 + i * 4 + g;
        ok[i] = ev[i] < E;
        int sv = ok[i] ? __ldg(eidx + ev[i]) : 0;
        int dv = ok[i] ? __ldg(eidx + E + ev[i]) : 0;
        pa[i] = Pbase + (((uint32_t)sv << 9) + loff);
        pb[i] = Pbase + (((uint32_t)dv << 9) + 256u + loff);
    }

    // issue all 24 gathers before any compute
    uint4 a0[3], a1[3], b0[3], b1[3];
    #pragma unroll
    for (int i = 0; i < 3; i++) {
        a0[i] = *reinterpret_cast<const uint4*>(pa[i]);
        a1[i] = *reinterpret_cast<const uint4*>(pa[i] + 128);
        b0[i] = *reinterpret_cast<const uint4*>(pb[i]);
        b1[i] = *reinterpret_cast<const uint4*>(pb[i] + 128);
    }

    const __half2 z2 = __float2half2_rn(0.0f);

    float acc[3];
    #pragma unroll
    for (int i = 0; i < 3; i++) {
        const uint32_t* qa0 = &a0[i].x;
        const uint32_t* qa1 = &a1[i].x;
        const uint32_t* qb0 = &b0[i].x;
        const uint32_t* qb1 = &b1[i].x;
        __half2 t = __hmul2(__hmax2(__hadd2(*reinterpret_cast<const __half2*>(&qa0[0]),
                                            *reinterpret_cast<const __half2*>(&qb0[0])), z2),
                            *reinterpret_cast<const __half2*>(&w2p0[0]));
        #pragma unroll
        for (int q = 1; q < 4; q++)
            t = __hfma2(__hmax2(__hadd2(*reinterpret_cast<const __half2*>(&qa0[q]),
                                        *reinterpret_cast<const __half2*>(&qb0[q])), z2),
                        *reinterpret_cast<const __half2*>(&w2p0[q]), t);
        #pragma unroll
        for (int q = 0; q < 4; q++)
            t = __hfma2(__hmax2(__hadd2(*reinterpret_cast<const __half2*>(&qa1[q]),
                                        *reinterpret_cast<const __half2*>(&qb1[q])), z2),
                        *reinterpret_cast<const __half2*>(&w2p1[q]), t);
        float2 f = __half22float2(t);
        acc[i] = f.x + f.y;
    }

    #pragma unroll
    for (int off = 4; off > 0; off >>= 1) {
        #pragma unroll
        for (int i = 0; i < 3; i++)
            acc[i] += __shfl_xor_sync(0xFFFFFFFFu, acc[i], off);
    }

    if (l8 == 0) {
        const float b2v = __ldg(b2);
        #pragma unroll
        for (int i = 0; i < 3; i++)
            if (ok[i]) out[ev[i]] = 1.0f / (1.0f + __expf(-(acc[i] + b2v)));
    }
}

// ---------------- launch ----------------

extern "C" void kernel_launch(void* const* d_in, const int* in_sizes, int n_in,
                              void* d_out, int out_size) {
    const float* hfeat = (const float*)d_in[0];
    const int*   eidx  = (const int*)d_in[1];
    const float* W1    = (const float*)d_in[2];
    const float* b1    = (const float*)d_in[3];
    const float* W2    = (const float*)d_in[4];
    const float* b2    = (const float*)d_in[5];
    float* out = (float*)d_out;

    const int M = in_sizes[0] / HID;
    const int E = in_sizes[1] / 2;
    const int n_tiles = (M + 63) / 64;

    cudaFuncSetAttribute(node_proj_kernel,
                         cudaFuncAttributeMaxDynamicSharedMemorySize, (int)P1_SMEM);

    int grid1 = 148;                         // 1 CTA/SM: W1 loaded once per SM
    if (grid1 > n_tiles) grid1 = n_tiles;
    node_proj_kernel<<<grid1, 256, P1_SMEM>>>(hfeat, W1, b1, M, n_tiles);

    const int warps = (E + 11) / 12;         // 12 edges per warp
    const int blocks = (warps + 7) / 8;
    edge_kernel<<<blocks, 256>>>(eidx, W2, b2, out, E);
}

// round 16
// speedup vs baseline: 1.0602x; 1.0293x over previous
#include <cuda_runtime.h>
#include <cuda_fp16.h>
#include <cstdint>

// ---------------------------------------------------------------------------
// Edge-MLP link predictor, factorized + tensor-core phase 1:
//   P[n][0:128]   = h[n] @ W1[0:128,:]   + b1   (Pa, fp16, PERMUTED layout)
//   P[n][128:256] = h[n] @ W1[128:256,:]        (Pb, fp16, PERMUTED layout)
//   out[e] = sigmoid( relu(Pa[src_e] + Pb[dst_e]) . W2 + b2 )
// Phase 1: persistent CTAs, 512 threads (16 warps -> 4/SMSP for latency
//          hiding), W1 SMEM-resident, double-buffered 128-row A tiles.
// Phase 2: 8 lanes/edge, 12 edges/warp, line-contiguous gathers
//          (one 128B line per LDG per edge = 4 wavefronts/edge floor).
// ---------------------------------------------------------------------------

static constexpr int HID = 128;
static constexpr int MAXN = 50000;

__device__ __half g_P[(size_t)MAXN * 256];

// ---------------- helpers ----------------

__device__ __forceinline__ uint32_t smem_u32(const void* p) {
    uint32_t a;
    asm("{ .reg .u64 t; cvta.to.shared.u64 t, %1; cvt.u32.u64 %0, t; }"
        : "=r"(a) : "l"(p));
    return a;
}

__device__ __forceinline__ uint32_t h2_bits(__half2 h) {
    return *reinterpret_cast<uint32_t*>(&h);
}

__device__ __forceinline__ void ldm_x4(uint32_t& a0, uint32_t& a1, uint32_t& a2,
                                       uint32_t& a3, uint32_t addr) {
    asm volatile("ldmatrix.sync.aligned.m8n8.x4.shared.b16 {%0,%1,%2,%3}, [%4];"
                 : "=r"(a0), "=r"(a1), "=r"(a2), "=r"(a3) : "r"(addr));
}

__device__ __forceinline__ void ldm_x4_t(uint32_t& b0, uint32_t& b1, uint32_t& b2,
                                         uint32_t& b3, uint32_t addr) {
    asm volatile("ldmatrix.sync.aligned.m8n8.x4.trans.shared.b16 {%0,%1,%2,%3}, [%4];"
                 : "=r"(b0), "=r"(b1), "=r"(b2), "=r"(b3) : "r"(addr));
}

__device__ __forceinline__ void mma16816(float& d0, float& d1, float& d2, float& d3,
                                         uint32_t a0, uint32_t a1, uint32_t a2,
                                         uint32_t a3, uint32_t b0, uint32_t b1) {
    asm volatile(
        "mma.sync.aligned.m16n8k16.row.col.f32.f16.f16.f32 "
        "{%0,%1,%2,%3}, {%4,%5,%6,%7}, {%8,%9}, {%0,%1,%2,%3};"
        : "+f"(d0), "+f"(d1), "+f"(d2), "+f"(d3)
        : "r"(a0), "r"(a1), "r"(a2), "r"(a3), "r"(b0), "r"(b1));
}

// ---------------- Phase 1: persistent node projection GEMM ----------------
// 512 threads, 128-row tiles, double-buffered A.

static constexpr int SROW = 136;
static constexpr uint32_t SROWB = SROW * 2;      // 272 bytes
static constexpr uint32_t AS_BYTES = 128u * SROWB;       // 34816
static constexpr uint32_t BS_BYTES = 256u * SROWB;       // 69632
static constexpr uint32_t P1_SMEM  = 2u * AS_BYTES + BS_BYTES;  // 139264

__global__ void __launch_bounds__(512, 1)
node_proj_kernel(const float* __restrict__ hfeat,
                 const float* __restrict__ W1,   // [256,128] row-major
                 const float* __restrict__ b1,   // [128]
                 int M, int n_tiles) {
    extern __shared__ __align__(16) char smem[];
    char* Bs = smem + 2 * AS_BYTES;           // [256][SROW] halfs
    const uint32_t as_b = smem_u32(smem);
    const uint32_t bs_b = smem_u32(Bs);

    const int tid = threadIdx.x;
    const int wid  = tid >> 5;                // 0..15
    const int lane = tid & 31;
    const int wm = (wid >> 2) * 32;           // 0,32,64,96
    const int wn = (wid & 3) * 32;            // 0,32,64,96
    const int l15 = lane & 15;
    const int khalf = (lane >> 4) * 8;
    const int r0 = lane >> 2;
    const int c0 = (lane & 3) * 2;
    const int brow = ((lane >> 3) & 1) * 8 + (lane & 7);
    const int bcol = (lane >> 4) * 8;

    // ---- load W1 (both halves) once: 8192 float4 over 512 threads ----
    #pragma unroll
    for (int it = 0; it < 16; it++) {
        int i  = tid + it * 512;
        int r  = i >> 5;
        int c4 = i & 31;
        float4 vb = reinterpret_cast<const float4*>(W1)[(size_t)r * 32 + c4];
        *reinterpret_cast<uint2*>(Bs + r * SROWB + c4 * 8) =
            make_uint2(h2_bits(__floats2half2_rn(vb.x, vb.y)),
                       h2_bits(__floats2half2_rn(vb.z, vb.w)));
    }

    // A-load mapping: 4096 float4 per 128-row tile over 512 threads -> 8 each
    const int ar  = tid >> 5;                 // base row 0..15
    const int ac4 = tid & 31;

    int tile = blockIdx.x;
    int buf  = 0;
    float4 va[8];
    if (tile < n_tiles) {
        const int m0 = tile * 128;
        #pragma unroll
        for (int it = 0; it < 8; it++) {
            int r = ar + it * 16;
            int gm = m0 + r; if (gm >= M) gm = M - 1;
            va[it] = reinterpret_cast<const float4*>(hfeat)[(size_t)gm * 32 + ac4];
        }
    }

    while (tile < n_tiles) {
        const int m0 = tile * 128;
        const int next = tile + gridDim.x;
        char* Acur = smem + buf * AS_BYTES;
        const uint32_t as_cur = as_b + buf * AS_BYTES;

        #pragma unroll
        for (int it = 0; it < 8; it++) {
            int r = ar + it * 16;
            *reinterpret_cast<uint2*>(Acur + r * SROWB + ac4 * 8) =
                make_uint2(h2_bits(__floats2half2_rn(va[it].x, va[it].y)),
                           h2_bits(__floats2half2_rn(va[it].z, va[it].w)));
        }
        __syncthreads();   // covers W1 STS on first iteration too

        // prefetch next tile's A while MMA runs
        if (next < n_tiles) {
            const int m1 = next * 128;
            #pragma unroll
            for (int it = 0; it < 8; it++) {
                int r = ar + it * 16;
                int gm = m1 + r; if (gm >= M) gm = M - 1;
                va[it] = reinterpret_cast<const float4*>(hfeat)[(size_t)gm * 32 + ac4];
            }
        }

        #pragma unroll
        for (int half = 0; half < 2; half++) {
            float d[2][4][4];
            #pragma unroll
            for (int fm = 0; fm < 2; fm++)
                #pragma unroll
                for (int fn = 0; fn < 4; fn++)
                    #pragma unroll
                    for (int r = 0; r < 4; r++) d[fm][fn][r] = 0.0f;

            const uint32_t bs_h = bs_b + (uint32_t)(half * 128) * SROWB;

            #pragma unroll
            for (int kk = 0; kk < 8; kk++) {
                const int k16 = kk * 16;
                uint32_t a[2][4];
                #pragma unroll
                for (int fm = 0; fm < 2; fm++) {
                    uint32_t addr = as_cur + (uint32_t)(wm + fm * 16 + l15) * SROWB +
                                    (uint32_t)(k16 + khalf) * 2;
                    ldm_x4(a[fm][0], a[fm][1], a[fm][2], a[fm][3], addr);
                }
                uint32_t b[4][2];
                #pragma unroll
                for (int fnp = 0; fnp < 2; fnp++) {
                    uint32_t addr = bs_h + (uint32_t)(k16 + brow) * SROWB +
                                    (uint32_t)(wn + fnp * 16 + bcol) * 2;
                    ldm_x4_t(b[2 * fnp][0], b[2 * fnp][1],
                             b[2 * fnp + 1][0], b[2 * fnp + 1][1], addr);
                }
                #pragma unroll
                for (int fm = 0; fm < 2; fm++)
                    #pragma unroll
                    for (int fn = 0; fn < 4; fn++)
                        mma16816(d[fm][fn][0], d[fm][fn][1], d[fm][fn][2], d[fm][fn][3],
                                 a[fm][0], a[fm][1], a[fm][2], a[fm][3],
                                 b[fn][0], b[fn][1]);
            }

            // epilogue: +b1, pack 8 halfs, one coalesced STG.128 per (fm,sub)
            float2 bias[4];
            #pragma unroll
            for (int fn = 0; fn < 4; fn++) {
                bias[fn] = (half == 0)
                    ? *reinterpret_cast<const float2*>(b1 + wn + fn * 8 + c0)
                    : make_float2(0.0f, 0.0f);
            }
            #pragma unroll
            for (int fm = 0; fm < 2; fm++) {
                #pragma unroll
                for (int sub = 0; sub < 2; sub++) {
                    int gm = m0 + wm + fm * 16 + r0 + sub * 8;
                    if (gm < M) {
                        uint32_t z[4];
                        #pragma unroll
                        for (int fn = 0; fn < 4; fn++) {
                            float x = d[fm][fn][sub * 2]     + bias[fn].x;
                            float y = d[fm][fn][sub * 2 + 1] + bias[fn].y;
                            z[fn] = h2_bits(__floats2half2_rn(x, y));
                        }
                        char* dst = reinterpret_cast<char*>(g_P) +
                                    (size_t)gm * 512 + half * 256 + wn * 2 +
                                    (lane & 3) * 16;
                        *reinterpret_cast<uint4*>(dst) = make_uint4(z[0], z[1], z[2], z[3]);
                    }
                }
            }
        }
        buf ^= 1;
        tile = next;
    }
}

// ---------------- Phase 2: 12 edges/warp, 8 lanes/edge, line-contiguous ----------------

__global__ void __launch_bounds__(256)
edge_kernel(const int* __restrict__ eidx,    // [2, E] int32
            const float* __restrict__ W2,    // [128]
            const float* __restrict__ b2,    // [1]
            float* __restrict__ out, int E) {
    __shared__ __align__(16) __half w2s[128];

    const int tid  = threadIdx.x;
    if (tid < 128) {
        int q = tid & 31;
        int j = (tid & ~31) + ((q >> 1) & 3) * 8 + (q >> 3) * 2 + (q & 1);
        w2s[tid] = __float2half_rn(__ldg(W2 + j));
    }
    __syncthreads();

    const int warp = (blockIdx.x * blockDim.x + tid) >> 5;
    const int lane = tid & 31;
    const int g  = lane >> 3;                // edge group 0..3
    const int l8 = lane & 7;                 // position within edge
    const int e0 = warp * 12;                // 12 edges per warp (3 batches of 4)
    if (e0 >= E) return;

    const char* w2c = reinterpret_cast<const char*>(w2s);
    uint4 wq0 = *reinterpret_cast<const uint4*>(w2c + l8 * 16);
    uint4 wq1 = *reinterpret_cast<const uint4*>(w2c + 128 + l8 * 16);
    const uint32_t* w2p0 = &wq0.x;
    const uint32_t* w2p1 = &wq1.x;

    const char* Pbase = reinterpret_cast<const char*>(g_P);
    const uint32_t loff = (uint32_t)l8 << 4;   // 16B chunk within 128B line

    int ev[3];
    bool ok[3];
    const char* pa[3];
    const char* pb[3];
    #pragma unroll
    for (int i = 0; i < 3; i++) {
        ev[i] = e0 + i * 4 + g;
        ok[i] = ev[i] < E;
        int sv = ok[i] ? __ldg(eidx + ev[i]) : 0;
        int dv = ok[i] ? __ldg(eidx + E + ev[i]) : 0;
        pa[i] = Pbase + (((uint32_t)sv << 9) + loff);
        pb[i] = Pbase + (((uint32_t)dv << 9) + 256u + loff);
    }

    // issue all 24 gathers before any compute
    uint4 a0[3], a1[3], b0[3], b1[3];
    #pragma unroll
    for (int i = 0; i < 3; i++) {
        a0[i] = *reinterpret_cast<const uint4*>(pa[i]);
        a1[i] = *reinterpret_cast<const uint4*>(pa[i] + 128);
        b0[i] = *reinterpret_cast<const uint4*>(pb[i]);
        b1[i] = *reinterpret_cast<const uint4*>(pb[i] + 128);
    }

    const __half2 z2 = __float2half2_rn(0.0f);

    float acc[3];
    #pragma unroll
    for (int i = 0; i < 3; i++) {
        const uint32_t* qa0 = &a0[i].x;
        const uint32_t* qa1 = &a1[i].x;
        const uint32_t* qb0 = &b0[i].x;
        const uint32_t* qb1 = &b1[i].x;
        __half2 t = __hmul2(__hmax2(__hadd2(*reinterpret_cast<const __half2*>(&qa0[0]),
                                            *reinterpret_cast<const __half2*>(&qb0[0])), z2),
                            *reinterpret_cast<const __half2*>(&w2p0[0]));
        #pragma unroll
        for (int q = 1; q < 4; q++)
            t = __hfma2(__hmax2(__hadd2(*reinterpret_cast<const __half2*>(&qa0[q]),
                                        *reinterpret_cast<const __half2*>(&qb0[q])), z2),
                        *reinterpret_cast<const __half2*>(&w2p0[q]), t);
        #pragma unroll
        for (int q = 0; q < 4; q++)
            t = __hfma2(__hmax2(__hadd2(*reinterpret_cast<const __half2*>(&qa1[q]),
                                        *reinterpret_cast<const __half2*>(&qb1[q])), z2),
                        *reinterpret_cast<const __half2*>(&w2p1[q]), t);
        float2 f = __half22float2(t);
        acc[i] = f.x + f.y;
    }

    #pragma unroll
    for (int off = 4; off > 0; off >>= 1) {
        #pragma unroll
        for (int i = 0; i < 3; i++)
            acc[i] += __shfl_xor_sync(0xFFFFFFFFu, acc[i], off);
    }

    if (l8 == 0) {
        const float b2v = __ldg(b2);
        #pragma unroll
        for (int i = 0; i < 3; i++)
            if (ok[i]) out[ev[i]] = 1.0f / (1.0f + __expf(-(acc[i] + b2v)));
    }
}

// ---------------- launch ----------------

extern "C" void kernel_launch(void* const* d_in, const int* in_sizes, int n_in,
                              void* d_out, int out_size) {
    const float* hfeat = (const float*)d_in[0];
    const int*   eidx  = (const int*)d_in[1];
    const float* W1    = (const float*)d_in[2];
    const float* b1    = (const float*)d_in[3];
    const float* W2    = (const float*)d_in[4];
    const float* b2    = (const float*)d_in[5];
    float* out = (float*)d_out;

    const int M = in_sizes[0] / HID;
    const int E = in_sizes[1] / 2;
    const int n_tiles = (M + 127) / 128;

    cudaFuncSetAttribute(node_proj_kernel,
                         cudaFuncAttributeMaxDynamicSharedMemorySize, (int)P1_SMEM);

    int grid1 = 148;                         // 1 CTA/SM: W1 loaded once per SM
    if (grid1 > n_tiles) grid1 = n_tiles;
    node_proj_kernel<<<grid1, 512, P1_SMEM>>>(hfeat, W1, b1, M, n_tiles);

    const int warps = (E + 11) / 12;         // 12 edges per warp
    const int blocks = (warps + 7) / 8;
    edge_kernel<<<blocks, 256>>>(eidx, W2, b2, out, E);
}